// round 1
// baseline (speedup 1.0000x reference)
#include <cuda_runtime.h>
#include <cuda_bf16.h>
#include <math.h>

// Problem constants
#define HT   128          // target H = W
#define HIN  64
#define CC   256          // channels
#define FF   128          // proj filters
#define BB   4            // batch
#define NU   32           // MLP units
#define DIN  118
#define KK2  9            // 3x3 taps
#define NOUT 2304         // C*K*K

#define PIF  3.14159265358979323846f

// Scratch (device globals: allocation-free rule)
__device__ float g_ker[(size_t)HT * HT * NOUT];          // [h][w][t][c]  ~151 MB
__device__ float g_y[(size_t)BB * HT * HT * CC];         // [b][h][w][c]  ~67 MB

// ---------------------------------------------------------------------------
// K1: hypernetwork. 1024 CTAs x 256 thr; CTA handles 16 pixels (row-major).
// ---------------------------------------------------------------------------
__global__ __launch_bounds__(256) void hyper_kernel(
    const float* __restrict__ W1, const float* __restrict__ b1,
    const float* __restrict__ W2, const float* __restrict__ b2,
    const float* __restrict__ W3, const float* __restrict__ b3,
    const float* __restrict__ W4, const float* __restrict__ b4,
    const float* __restrict__ Wo, const float* __restrict__ bo)
{
    __shared__ float feat[16][120];
    __shared__ float xa[16][32];
    __shared__ float xb[16][32];
    __shared__ float x4t[32][16];   // transposed final hidden layer

    const int tid  = threadIdx.x;
    const int pix0 = blockIdx.x * 16;

    // ---- features ----
    for (int idx = tid; idx < 16 * DIN; idx += 256) {
        int p  = idx / DIN;
        int fi = idx - p * DIN;
        int pix = pix0 + p;
        int h = pix >> 7, w = pix & 127;
        float v;
        if (fi < 50) {
            int i   = (fi < 25) ? fi : fi - 25;
            float x = ((fi < 25) ? (float)h : (float)w) * (1.0f / 127.0f);
            float f = 1.0f + (float)i * (1.0f / 24.0f);
            v = cosf(PIF * (2.0f * x + 1.0f) * f);
        } else if (fi < 100) {
            int i   = (fi - 50) % 25;
            float f = 1.0f + (float)i * (1.0f / 24.0f);
            v = cosf(PIF * 5.0f * f);             // scale coords are both 2.0
        } else {
            v = -1.0f;                             // kernel_enc is exactly -1
        }
        feat[p][fi] = v;
    }
    __syncthreads();

    // ---- layer 1: 118 -> 32 ----
    for (int o = tid; o < 16 * NU; o += 256) {
        int p = o >> 5, j = o & 31;
        float s = b1[j];
        #pragma unroll 2
        for (int k = 0; k < DIN; ++k) s += feat[p][k] * W1[k * NU + j];
        xa[p][j] = fmaxf(s, 0.0f);
    }
    __syncthreads();

    // ---- layer 2 ----
    for (int o = tid; o < 16 * NU; o += 256) {
        int p = o >> 5, j = o & 31;
        float s = b2[j];
        #pragma unroll
        for (int k = 0; k < NU; ++k) s += xa[p][k] * W2[k * NU + j];
        xb[p][j] = fmaxf(s, 0.0f);
    }
    __syncthreads();

    // ---- layer 3 ----
    for (int o = tid; o < 16 * NU; o += 256) {
        int p = o >> 5, j = o & 31;
        float s = b3[j];
        #pragma unroll
        for (int k = 0; k < NU; ++k) s += xb[p][k] * W3[k * NU + j];
        xa[p][j] = fmaxf(s, 0.0f);
    }
    __syncthreads();

    // ---- layer 4 (store transposed) ----
    for (int o = tid; o < 16 * NU; o += 256) {
        int p = o >> 5, j = o & 31;
        float s = b4[j];
        #pragma unroll
        for (int k = 0; k < NU; ++k) s += xa[p][k] * W4[k * NU + j];
        x4t[j][p] = fmaxf(s, 0.0f);
    }
    __syncthreads();

    // ---- output layer: [16 x 32] @ [32 x 2304] ----
    // thread tid owns channel c = tid; loops t = 0..8 (j = t*256 + c)
    const int c = tid;
    for (int t = 0; t < 9; ++t) {
        const int j = t * CC + c;
        float acc[16];
        const float bj = bo[j];
        #pragma unroll
        for (int p = 0; p < 16; ++p) acc[p] = bj;

        #pragma unroll 4
        for (int kk = 0; kk < NU; ++kk) {
            float wv = Wo[kk * NOUT + j];
            const float4* xv = (const float4*)&x4t[kk][0];
            #pragma unroll
            for (int q = 0; q < 4; ++q) {
                float4 x4 = xv[q];
                acc[q * 4 + 0] += x4.x * wv;
                acc[q * 4 + 1] += x4.y * wv;
                acc[q * 4 + 2] += x4.z * wv;
                acc[q * 4 + 3] += x4.w * wv;
            }
        }
        #pragma unroll
        for (int p = 0; p < 16; ++p)
            g_ker[(size_t)(pix0 + p) * NOUT + j] = acc[p];
    }
}

// ---------------------------------------------------------------------------
// K2: per-pixel 3x3 weighted patch sum on nearest-upsampled input.
// grid = 16384 (one pixel), 256 threads (one channel each), all 4 batches.
// ---------------------------------------------------------------------------
__global__ __launch_bounds__(256) void conv_kernel(const float* __restrict__ main_in)
{
    const int pix = blockIdx.x;
    const int c   = threadIdx.x;
    const int h   = pix >> 7, w = pix & 127;

    float kv[9];
    const float* kp = &g_ker[(size_t)pix * NOUT + c];
    #pragma unroll
    for (int t = 0; t < 9; ++t) kv[t] = kp[t * CC];

    #pragma unroll
    for (int b = 0; b < BB; ++b) {
        float y = 0.0f;
        #pragma unroll
        for (int di = 0; di < 3; ++di) {
            int hh = h + di - 1;
            if ((unsigned)hh < (unsigned)HT) {
                int sr = hh >> 1;
                const float* rowp = main_in + (((size_t)b * HIN + sr) * HIN) * CC + c;
                #pragma unroll
                for (int dj = 0; dj < 3; ++dj) {
                    int ww = w + dj - 1;
                    if ((unsigned)ww < (unsigned)HT)
                        y += rowp[(size_t)(ww >> 1) * CC] * kv[di * 3 + dj];
                }
            }
        }
        g_y[(((size_t)b * HT + h) * HT + w) * CC + c] = y;
    }
}

// ---------------------------------------------------------------------------
// K3: projection GEMM. C[M=65536, N=128] = Y[M,256] @ Wp[256,128] + b_proj
// 128x128 CTA tile, 8x8 per thread, BK=16.
// ---------------------------------------------------------------------------
#define BM 128
#define BN 128
#define BK 16

__global__ __launch_bounds__(256) void proj_gemm(
    const float* __restrict__ Wp, const float* __restrict__ bproj,
    float* __restrict__ out)
{
    __shared__ float As[BK][BM + 4];   // transposed A tile (+pad)
    __shared__ float Bs[BK][BN];

    const int tid = threadIdx.x;
    const int m0  = blockIdx.x * BM;
    const int tx  = tid & 15;           // N sub-tile
    const int ty  = tid >> 4;           // M sub-tile

    // A load mapping: 2 float4 per thread
    const int arow = tid >> 2;          // 0..63
    const int acol = (tid & 3) * 4;     // 0,4,8,12
    // B load mapping: 2 float4 per thread
    const int brow = tid >> 5;          // 0..7
    const int bcol = (tid & 31) * 4;    // 0..124

    float acc[8][8];
    #pragma unroll
    for (int i = 0; i < 8; ++i)
        #pragma unroll
        for (int j = 0; j < 8; ++j) acc[i][j] = 0.0f;

    const float* Y = g_y;

    for (int k0 = 0; k0 < CC; k0 += BK) {
        float4 a0 = *(const float4*)&Y[(size_t)(m0 + arow)      * CC + k0 + acol];
        float4 a1 = *(const float4*)&Y[(size_t)(m0 + arow + 64) * CC + k0 + acol];
        float4 bv0 = *(const float4*)&Wp[(size_t)(k0 + brow)     * FF + bcol];
        float4 bv1 = *(const float4*)&Wp[(size_t)(k0 + brow + 8) * FF + bcol];

        if (k0) __syncthreads();
        As[acol + 0][arow]      = a0.x;
        As[acol + 1][arow]      = a0.y;
        As[acol + 2][arow]      = a0.z;
        As[acol + 3][arow]      = a0.w;
        As[acol + 0][arow + 64] = a1.x;
        As[acol + 1][arow + 64] = a1.y;
        As[acol + 2][arow + 64] = a1.z;
        As[acol + 3][arow + 64] = a1.w;
        *(float4*)&Bs[brow][bcol]     = bv0;
        *(float4*)&Bs[brow + 8][bcol] = bv1;
        __syncthreads();

        #pragma unroll
        for (int k = 0; k < BK; ++k) {
            float4 av0 = *(const float4*)&As[k][ty * 8];
            float4 av1 = *(const float4*)&As[k][ty * 8 + 4];
            float4 bw0 = *(const float4*)&Bs[k][tx * 8];
            float4 bw1 = *(const float4*)&Bs[k][tx * 8 + 4];
            float a[8] = {av0.x, av0.y, av0.z, av0.w, av1.x, av1.y, av1.z, av1.w};
            float b[8] = {bw0.x, bw0.y, bw0.z, bw0.w, bw1.x, bw1.y, bw1.z, bw1.w};
            #pragma unroll
            for (int i = 0; i < 8; ++i)
                #pragma unroll
                for (int j = 0; j < 8; ++j)
                    acc[i][j] += a[i] * b[j];
        }
    }

    // epilogue
    #pragma unroll
    for (int i = 0; i < 8; ++i) {
        const size_t m = (size_t)(m0 + ty * 8 + i);
        #pragma unroll
        for (int j = 0; j < 8; j += 4) {
            int n = tx * 8 + j;
            float4 r;
            r.x = acc[i][j + 0] + bproj[n + 0];
            r.y = acc[i][j + 1] + bproj[n + 1];
            r.z = acc[i][j + 2] + bproj[n + 2];
            r.w = acc[i][j + 3] + bproj[n + 3];
            *(float4*)&out[m * FF + n] = r;
        }
    }
}

// ---------------------------------------------------------------------------
extern "C" void kernel_launch(void* const* d_in, const int* in_sizes, int n_in,
                              void* d_out, int out_size)
{
    const float* main_in = (const float*)d_in[0];
    // d_in[1] = skip_connection (shape-only, unused)
    const float* W1 = (const float*)d_in[2];
    const float* b1 = (const float*)d_in[3];
    const float* W2 = (const float*)d_in[4];
    const float* b2 = (const float*)d_in[5];
    const float* W3 = (const float*)d_in[6];
    const float* b3 = (const float*)d_in[7];
    const float* W4 = (const float*)d_in[8];
    const float* b4 = (const float*)d_in[9];
    const float* Wo = (const float*)d_in[10];
    const float* bo = (const float*)d_in[11];
    const float* Wp = (const float*)d_in[12];
    const float* bp = (const float*)d_in[13];
    float* out = (float*)d_out;

    hyper_kernel<<<1024, 256>>>(W1, b1, W2, b2, W3, b3, W4, b4, Wo, bo);
    conv_kernel<<<HT * HT, 256>>>(main_in);
    proj_gemm<<<(BB * HT * HT) / BM, 256>>>(Wp, bp, out);
}